// round 17
// baseline (speedup 1.0000x reference)
#include <cuda_runtime.h>
#include <cstdint>

// ---------------------------------------------------------------------------
// B=2, N=1024, D=1024, K=8 (circulant), H=16, dh=64
// All GEMM/flash operands pre-rounded to tf32 in gmem => no cvt in hot loops.
// Weights expanded TRANSPOSED: Wt[n][k] = W[k][n]  (k contiguous)
// V is produced directly TRANSPOSED by the QKV GEMM: Vt[b][col][seq]
// Out-projection: split-K=2 (occupancy) + fixed-order reduce.
// ---------------------------------------------------------------------------
constexpr int DD = 1024;
constexpr int MM = 2048;

__device__ float g_We[4][DD * DD];   // expanded weights (tf32-rounded), Wt[n][k]
__device__ float g_X[MM * DD];       // x, tf32-rounded
__device__ float g_Q[MM * DD];       // tf32-rounded
__device__ float g_K[MM * DD];       // tf32-rounded
__device__ float g_Vt[MM * DD];      // V transposed per batch, tf32-rounded
__device__ float g_O[MM * DD];       // attention out, tf32-rounded
__device__ float g_P[2][MM * DD];    // out-proj split-K partials

__device__ __forceinline__ uint32_t f2tf32(float f) {
    uint32_t r;
    asm("cvt.rna.tf32.f32 %0, %1;" : "=r"(r) : "f"(f));
    return r;
}

#define MMA_TF32(ACC, A0, A1, A2, A3, B0, B1)                            \
    asm volatile(                                                        \
        "mma.sync.aligned.m16n8k8.row.col.f32.tf32.tf32.f32 "            \
        "{%0,%1,%2,%3}, {%4,%5,%6,%7}, {%8,%9}, {%0,%1,%2,%3};"          \
        : "+f"((ACC)[0]), "+f"((ACC)[1]), "+f"((ACC)[2]), "+f"((ACC)[3]) \
        : "r"(A0), "r"(A1), "r"(A2), "r"(A3), "r"(B0), "r"(B1))

#define LDSM4(R0, R1, R2, R3, ADDR)                                      \
    asm volatile("ldmatrix.sync.aligned.m8n8.x4.shared.b16 "             \
                 "{%0,%1,%2,%3}, [%4];"                                  \
                 : "=r"(R0), "=r"(R1), "=r"(R2), "=r"(R3) : "r"(ADDR))

__device__ __forceinline__ void cp16(uint32_t smem, const void* g) {
    asm volatile("cp.async.ca.shared.global [%0], [%1], 16;\n"
                 :: "r"(smem), "l"(g));
}

extern __shared__ uint32_t dynsm[];

// ---------------------------------------------------------------------------
// Prep: expand circulant weights (y=0..3) + tf32-round x (y=4,5)
// ---------------------------------------------------------------------------
__global__ void prep_kernel(const float* __restrict__ w0,
                            const float* __restrict__ w1,
                            const float* __restrict__ w2,
                            const float* __restrict__ w3,
                            const float* __restrict__ x)
{
    int idx = blockIdx.x * 256 + threadIdx.x;
    int y = blockIdx.y;
    if (y < 4) {
        const float* w;
        switch (y) {
            case 0:  w = w0; break;
            case 1:  w = w1; break;
            case 2:  w = w2; break;
            default: w = w3; break;
        }
        int n = idx >> 10;
        int k = idx & 1023;
        g_We[y][idx] = __uint_as_float(
            f2tf32(w[((n >> 3) << 10) + ((k >> 3) << 3) + ((n - k) & 7)]));
    } else {
        int base = (y - 4) * (1 << 20);
        g_X[base + idx] = __uint_as_float(f2tf32(x[base + idx]));
    }
}

// ---------------------------------------------------------------------------
// Shared GEMM machinery: 128x128 tile, BK=16, 8 warps of 32x64, ldmatrix
// frags, 4-stage cp.async pipeline, one barrier per iteration.
// KITERS: k-iterations (64 full-K, 32 split-K).
// ---------------------------------------------------------------------------
constexpr int GST  = 20;
constexpr int BUFW = 128 * GST;
constexpr int NST  = 4;
constexpr int GEMM_SMEM = 2 * NST * BUFW * 4;   // 81920 bytes

struct GemmCtx {
    const float* Ap;
    const float* Bp;
    uint32_t sA0, sA1, sB0, sB1;
    uint32_t aAddr[2];
    uint32_t bAddr[4];
};

__device__ __forceinline__ void gemm_setup(GemmCtx& g, const float* A,
                                           const float* Bm, int cRow, int cCol,
                                           int kBeg)
{
    const int tid  = threadIdx.x;
    const int warp = tid >> 5;
    const int lane = tid & 31;
    const int wm   = (warp & 3) * 32;
    const int wn   = (warp >> 2) * 64;
    const int sr = tid >> 2;
    const int sc = (tid & 3) * 4;

    g.Ap = A  + (size_t)(cRow + sr) * DD + kBeg + sc;
    g.Bp = Bm + (size_t)(cCol + sr) * DD + kBeg + sc;

    const uint32_t aBase = (uint32_t)__cvta_generic_to_shared(dynsm);
    const uint32_t bBase = aBase + NST * BUFW * 4;
    g.sA0 = aBase + (sr * GST + sc) * 4;
    g.sA1 = g.sA0 + 64 * GST * 4;
    g.sB0 = bBase + (sr * GST + sc) * 4;
    g.sB1 = g.sB0 + 64 * GST * 4;

#pragma unroll
    for (int mi = 0; mi < 2; mi++)
        g.aAddr[mi] = aBase + ((wm + mi * 16 + (lane & 15)) * GST) * 4 +
                      (lane >> 4) * 16;
#pragma unroll
    for (int p = 0; p < 4; p++)
        g.bAddr[p] = bBase +
                     ((wn + (2 * p + (lane >> 4)) * 8 + (lane & 7)) * GST) * 4 +
                     ((lane >> 3) & 1) * 16;
}

__device__ __forceinline__ void gemm_issue(const GemmCtx& g, int s, int kb)
{
    const uint32_t so = (uint32_t)s * (BUFW * 4);
    cp16(g.sA0 + so, g.Ap + kb);
    cp16(g.sA1 + so, g.Ap + 64 * DD + kb);
    cp16(g.sB0 + so, g.Bp + kb);
    cp16(g.sB1 + so, g.Bp + 64 * DD + kb);
    asm volatile("cp.async.commit_group;");
}

__device__ __forceinline__ void gemm_compute(const GemmCtx& g, int it,
                                             float acc[2][8][4])
{
    const uint32_t so = (uint32_t)(it & 3) * (BUFW * 4);
#pragma unroll
    for (int kc = 0; kc < 2; kc++) {
        const uint32_t ko = so + kc * 32;
        uint32_t a0[4], a1[4];
        LDSM4(a0[0], a0[1], a0[2], a0[3], g.aAddr[0] + ko);
        LDSM4(a1[0], a1[1], a1[2], a1[3], g.aAddr[1] + ko);
        uint32_t bv[4][4];
#pragma unroll
        for (int p = 0; p < 4; p++)
            LDSM4(bv[p][0], bv[p][1], bv[p][2], bv[p][3], g.bAddr[p] + ko);
#pragma unroll
        for (int p = 0; p < 4; p++) {
            MMA_TF32(acc[0][2 * p],     a0[0], a0[1], a0[2], a0[3], bv[p][0], bv[p][1]);
            MMA_TF32(acc[0][2 * p + 1], a0[0], a0[1], a0[2], a0[3], bv[p][2], bv[p][3]);
            MMA_TF32(acc[1][2 * p],     a1[0], a1[1], a1[2], a1[3], bv[p][0], bv[p][1]);
            MMA_TF32(acc[1][2 * p + 1], a1[0], a1[1], a1[2], a1[3], bv[p][2], bv[p][3]);
        }
    }
}

template <int KITERS>
__device__ __forceinline__ void gemm_mainloop(const GemmCtx& g,
                                              float acc[2][8][4])
{
    gemm_issue(g, 0, 0);
    gemm_issue(g, 1, 16);
    gemm_issue(g, 2, 32);
    for (int it = 0; it <= KITERS - 4; it++) {
        asm volatile("cp.async.wait_group 2;");
        __syncthreads();
        gemm_issue(g, (it + 3) & 3, (it + 3) * 16);
        gemm_compute(g, it, acc);
    }
    asm volatile("cp.async.wait_group 2;");
    __syncthreads();
    gemm_compute(g, KITERS - 3, acc);
    asm volatile("cp.async.wait_group 1;");
    __syncthreads();
    gemm_compute(g, KITERS - 2, acc);
    asm volatile("cp.async.wait_group 0;");
    __syncthreads();
    gemm_compute(g, KITERS - 1, acc);
}

// ---------------------------------------------------------------------------
// QKV GEMM: z in {0,1,2}; output tf32-rounded; z==2 stored transposed (Vt).
// ---------------------------------------------------------------------------
__global__ __launch_bounds__(256, 2)
void gemm_qkv(const float* __restrict__ A,
              const float* __restrict__ bi0, const float* __restrict__ bi1,
              const float* __restrict__ bi2,
              float* __restrict__ C0, float* __restrict__ C1,
              float* __restrict__ C2)
{
    const float* Bm  = g_We[blockIdx.z];
    const float* bias = (blockIdx.z == 0) ? bi0 : (blockIdx.z == 1) ? bi1 : bi2;
    float* C = (blockIdx.z == 0) ? C0 : (blockIdx.z == 1) ? C1 : C2;

    const int tid  = threadIdx.x;
    const int warp = tid >> 5;
    const int lane = tid & 31;
    const int grp  = lane >> 2;
    const int q    = lane & 3;
    const int cRow = blockIdx.y * 128;
    const int cCol = blockIdx.x * 128;
    const int wm   = (warp & 3) * 32;
    const int wn   = (warp >> 2) * 64;

    GemmCtx g;
    gemm_setup(g, A, Bm, cRow, cCol, 0);

    float acc[2][8][4];
#pragma unroll
    for (int mi = 0; mi < 2; mi++)
#pragma unroll
        for (int ni = 0; ni < 8; ni++)
#pragma unroll
            for (int c = 0; c < 4; c++) acc[mi][ni][c] = 0.f;

    gemm_mainloop<64>(g, acc);

#pragma unroll
    for (int mi = 0; mi < 2; mi++) {
#pragma unroll
        for (int ni = 0; ni < 8; ni++) {
            int row = cRow + wm + mi * 16 + grp;
            int col = cCol + wn + ni * 8 + q * 2;
            float bx = bias[col], by = bias[col + 1];
            float v0 = __uint_as_float(f2tf32(acc[mi][ni][0] + bx));
            float v1 = __uint_as_float(f2tf32(acc[mi][ni][1] + by));
            float v2 = __uint_as_float(f2tf32(acc[mi][ni][2] + bx));
            float v3 = __uint_as_float(f2tf32(acc[mi][ni][3] + by));
            if (blockIdx.z == 2) {
                size_t bb  = ((size_t)(row >> 10)) << 20;
                int seq = row & 1023;
                C[bb + (size_t)col * 1024 + seq]           = v0;
                C[bb + (size_t)(col + 1) * 1024 + seq]     = v1;
                C[bb + (size_t)col * 1024 + seq + 8]       = v2;
                C[bb + (size_t)(col + 1) * 1024 + seq + 8] = v3;
            } else {
                *(float2*)(C + (size_t)row * DD + col)       = make_float2(v0, v1);
                *(float2*)(C + (size_t)(row + 8) * DD + col) = make_float2(v2, v3);
            }
        }
    }
}

// ---------------------------------------------------------------------------
// Out-projection: split-K=2. blockIdx.z = split; partial (no bias) -> g_P[z].
// ---------------------------------------------------------------------------
__global__ __launch_bounds__(256, 2)
void gemm_out_sk(const float* __restrict__ A, const float* __restrict__ Bm)
{
    const int split = blockIdx.z;
    float* C = g_P[split];

    const int tid  = threadIdx.x;
    const int warp = tid >> 5;
    const int lane = tid & 31;
    const int grp  = lane >> 2;
    const int q    = lane & 3;
    const int cRow = blockIdx.y * 128;
    const int cCol = blockIdx.x * 128;
    const int wm   = (warp & 3) * 32;
    const int wn   = (warp >> 2) * 64;

    GemmCtx g;
    gemm_setup(g, A, Bm, cRow, cCol, split * 512);

    float acc[2][8][4];
#pragma unroll
    for (int mi = 0; mi < 2; mi++)
#pragma unroll
        for (int ni = 0; ni < 8; ni++)
#pragma unroll
            for (int c = 0; c < 4; c++) acc[mi][ni][c] = 0.f;

    gemm_mainloop<32>(g, acc);

#pragma unroll
    for (int mi = 0; mi < 2; mi++) {
#pragma unroll
        for (int ni = 0; ni < 8; ni++) {
            int row = cRow + wm + mi * 16 + grp;
            int col = cCol + wn + ni * 8 + q * 2;
            *(float2*)(C + (size_t)row * DD + col) =
                make_float2(acc[mi][ni][0], acc[mi][ni][1]);
            *(float2*)(C + (size_t)(row + 8) * DD + col) =
                make_float2(acc[mi][ni][2], acc[mi][ni][3]);
        }
    }
}

// out = p0 + p1 + bias  (fixed order, deterministic)
__global__ __launch_bounds__(256)
void reduce_bias(const float* __restrict__ bias, float* __restrict__ out)
{
    int idx = (blockIdx.x * 256 + threadIdx.x) * 4;
    float4 a = *(const float4*)(g_P[0] + idx);
    float4 b = *(const float4*)(g_P[1] + idx);
    float4 bv = *(const float4*)(bias + (idx & 1023));
    float4 r;
    r.x = a.x + b.x + bv.x;
    r.y = a.y + b.y + bv.y;
    r.z = a.z + b.z + bv.z;
    r.w = a.w + b.w + bv.w;
    *(float4*)(out + idx) = r;
}

// ---------------------------------------------------------------------------
// Tensor-core causal flash attention (R16 version: pure-copy staging,
// private P smem, 2 barriers/tile).
// ---------------------------------------------------------------------------
constexpr int FST  = 68;
constexpr int FBUF = 64 * FST;
constexpr int FLASH_SMEM = 3 * FBUF * 4;   // 52224 bytes

__global__ __launch_bounds__(128, 3)
void flash_mma(const float* __restrict__ Qg, const float* __restrict__ Kg,
               const float* __restrict__ Vtg, float* __restrict__ Og)
{
    const int tid  = threadIdx.x;
    const int warp = tid >> 5;
    const int lane = tid & 31;
    const int grp  = lane >> 2;
    const int q    = lane & 3;

    const int qb = 15 - blockIdx.y;
    const int i0 = qb * 64;
    const int h  = blockIdx.x & 15;
    const int b  = blockIdx.x >> 4;
    const size_t base   = (size_t)b * (1024 * 1024) + h * 64;
    const size_t vtbase = (size_t)b * (1024 * 1024) + (size_t)(h * 64) * 1024;

    const int wm = warp * 16;
    const int r0 = i0 + wm + grp;

    uint32_t* Ksm = dynsm;
    uint32_t* Vsm = dynsm + FBUF;
    uint32_t* Psm = dynsm + 2 * FBUF;

    const uint32_t kBase = (uint32_t)__cvta_generic_to_shared(Ksm);
    const uint32_t vBase = (uint32_t)__cvta_generic_to_shared(Vsm);
    const uint32_t pBase = (uint32_t)__cvta_generic_to_shared(Psm);
    uint32_t kAddr[4], vAddr[4];
#pragma unroll
    for (int p = 0; p < 4; p++) {
        int nr = (2 * p + (lane >> 4)) * 8 + (lane & 7);
        kAddr[p] = kBase + nr * FST * 4 + ((lane >> 3) & 1) * 16;
        vAddr[p] = vBase + nr * FST * 4 + ((lane >> 3) & 1) * 16;
    }
    const uint32_t pAddr = pBase + (wm + (lane & 15)) * FST * 4 + (lane >> 4) * 16;
    uint32_t* Pw = Psm + wm * FST;

#pragma unroll
    for (int it = 0; it < 8; it++) {
        int idx = tid + it * 128;
        int row = idx >> 4;
        int c4  = (idx & 15) << 2;
        *(float4*)&((float*)Vsm)[row * FST + c4] =
            *(const float4*)(Qg + base + (size_t)(i0 + row) * DD + c4);
    }
    __syncthreads();
    uint32_t qf[8][4];
    {
        const float* Qs = (const float*)Vsm;
#pragma unroll
        for (int ks = 0; ks < 8; ks++) {
            qf[ks][0] = f2tf32(Qs[(wm + grp)     * FST + ks * 8 + q] * 0.125f);
            qf[ks][1] = f2tf32(Qs[(wm + grp + 8) * FST + ks * 8 + q] * 0.125f);
            qf[ks][2] = f2tf32(Qs[(wm + grp)     * FST + ks * 8 + q + 4] * 0.125f);
            qf[ks][3] = f2tf32(Qs[(wm + grp + 8) * FST + ks * 8 + q + 4] * 0.125f);
        }
    }
    __syncthreads();

    float oacc[8][4];
#pragma unroll
    for (int nt = 0; nt < 8; nt++)
#pragma unroll
        for (int c = 0; c < 4; c++) oacc[nt][c] = 0.f;
    float m0 = -1e30f, m1 = -1e30f, l0 = 0.f, l1 = 0.f;

    for (int jb = 0; jb <= qb; jb++) {
        const int j0 = jb * 64;

#pragma unroll
        for (int it = 0; it < 8; it++) {
            int idx = tid + it * 128;
            int row = idx >> 4;
            int c4  = (idx & 15) << 2;
            *(uint4*)&Ksm[row * FST + c4] =
                *(const uint4*)(Kg + base + (size_t)(j0 + row) * DD + c4);
            *(uint4*)&Vsm[row * FST + c4] =
                *(const uint4*)(Vtg + vtbase + (size_t)row * 1024 + j0 + c4);
        }
        __syncthreads();

        float sacc[8][4];
#pragma unroll
        for (int nt = 0; nt < 8; nt++)
#pragma unroll
            for (int c = 0; c < 4; c++) sacc[nt][c] = 0.f;
#pragma unroll
        for (int ks = 0; ks < 8; ks++) {
            uint32_t kb[4][4];
#pragma unroll
            for (int p = 0; p < 4; p++)
                LDSM4(kb[p][0], kb[p][1], kb[p][2], kb[p][3], kAddr[p] + ks * 32);
#pragma unroll
            for (int p = 0; p < 4; p++) {
                MMA_TF32(sacc[2 * p],     qf[ks][0], qf[ks][1], qf[ks][2], qf[ks][3],
                         kb[p][0], kb[p][1]);
                MMA_TF32(sacc[2 * p + 1], qf[ks][0], qf[ks][1], qf[ks][2], qf[ks][3],
                         kb[p][2], kb[p][3]);
            }
        }

        const bool diag = (jb == qb);
        float mx0 = -1e30f, mx1 = -1e30f;
#pragma unroll
        for (int nt = 0; nt < 8; nt++) {
            float s0 = sacc[nt][0];
            float s1 = sacc[nt][1];
            float s2 = sacc[nt][2];
            float s3 = sacc[nt][3];
            if (diag) {
                int j = j0 + nt * 8 + q * 2;
                if (j     > r0)     s0 = -1e30f;
                if (j + 1 > r0)     s1 = -1e30f;
                if (j     > r0 + 8) s2 = -1e30f;
                if (j + 1 > r0 + 8) s3 = -1e30f;
            }
            sacc[nt][0] = s0; sacc[nt][1] = s1;
            sacc[nt][2] = s2; sacc[nt][3] = s3;
            mx0 = fmaxf(mx0, fmaxf(s0, s1));
            mx1 = fmaxf(mx1, fmaxf(s2, s3));
        }
        mx0 = fmaxf(mx0, __shfl_xor_sync(0xffffffffu, mx0, 1));
        mx0 = fmaxf(mx0, __shfl_xor_sync(0xffffffffu, mx0, 2));
        mx1 = fmaxf(mx1, __shfl_xor_sync(0xffffffffu, mx1, 1));
        mx1 = fmaxf(mx1, __shfl_xor_sync(0xffffffffu, mx1, 2));
        float mn0 = fmaxf(m0, mx0), mn1 = fmaxf(m1, mx1);
        float al0 = __expf(m0 - mn0), al1 = __expf(m1 - mn1);
        m0 = mn0; m1 = mn1;
        float ps0 = 0.f, ps1 = 0.f;
#pragma unroll
        for (int nt = 0; nt < 8; nt++) {
            float p0 = __expf(sacc[nt][0] - mn0);
            float p1 = __expf(sacc[nt][1] - mn0);
            float p2 = __expf(sacc[nt][2] - mn1);
            float p3 = __expf(sacc[nt][3] - mn1);
            ps0 += p0 + p1;
            ps1 += p2 + p3;
            sacc[nt][0] = p0; sacc[nt][1] = p1;
            sacc[nt][2] = p2; sacc[nt][3] = p3;
        }
        l0 = l0 * al0 + ps0;
        l1 = l1 * al1 + ps1;
#pragma unroll
        for (int nt = 0; nt < 8; nt++) {
            oacc[nt][0] *= al0; oacc[nt][1] *= al0;
            oacc[nt][2] *= al1; oacc[nt][3] *= al1;
        }

#pragma unroll
        for (int nt = 0; nt < 8; nt++) {
            *(uint2*)&Pw[grp * FST + nt * 8 + q * 2] =
                make_uint2(f2tf32(sacc[nt][0]), f2tf32(sacc[nt][1]));
            *(uint2*)&Pw[(grp + 8) * FST + nt * 8 + q * 2] =
                make_uint2(f2tf32(sacc[nt][2]), f2tf32(sacc[nt][3]));
        }
        __syncwarp();

#pragma unroll
        for (int ks = 0; ks < 8; ks++) {
            uint32_t af[4];
            LDSM4(af[0], af[1], af[2], af[3], pAddr + ks * 32);
            uint32_t vb[4][4];
#pragma unroll
            for (int p = 0; p < 4; p++)
                LDSM4(vb[p][0], vb[p][1], vb[p][2], vb[p][3], vAddr[p] + ks * 32);
#pragma unroll
            for (int p = 0; p < 4; p++) {
                MMA_TF32(oacc[2 * p],     af[0], af[1], af[2], af[3], vb[p][0], vb[p][1]);
                MMA_TF32(oacc[2 * p + 1], af[0], af[1], af[2], af[3], vb[p][2], vb[p][3]);
            }
        }
        __syncthreads();
    }

    l0 += __shfl_xor_sync(0xffffffffu, l0, 1);
    l0 += __shfl_xor_sync(0xffffffffu, l0, 2);
    l1 += __shfl_xor_sync(0xffffffffu, l1, 1);
    l1 += __shfl_xor_sync(0xffffffffu, l1, 2);
    const float inv0 = 1.f / l0;
    const float inv1 = 1.f / l1;

#pragma unroll
    for (int nt = 0; nt < 8; nt++) {
        int col = nt * 8 + q * 2;
        uint2 w0 = make_uint2(f2tf32(oacc[nt][0] * inv0), f2tf32(oacc[nt][1] * inv0));
        uint2 w1 = make_uint2(f2tf32(oacc[nt][2] * inv1), f2tf32(oacc[nt][3] * inv1));
        *(uint2*)(Og + base + (size_t)r0 * DD + col) = w0;
        *(uint2*)(Og + base + (size_t)(r0 + 8) * DD + col) = w1;
    }
}

// ---------------------------------------------------------------------------
extern "C" void kernel_launch(void* const* d_in, const int* in_sizes, int n_in,
                              void* d_out, int out_size)
{
    (void)in_sizes; (void)n_in; (void)out_size;
    const float* x  = (const float*)d_in[0];
    const float* wq = (const float*)d_in[2];
    const float* bq = (const float*)d_in[3];
    const float* wk = (const float*)d_in[4];
    const float* bk = (const float*)d_in[5];
    const float* wv = (const float*)d_in[6];
    const float* bv = (const float*)d_in[7];
    const float* wo = (const float*)d_in[8];
    const float* bo = (const float*)d_in[9];
    float* out = (float*)d_out;

    float *We, *X, *Qb, *Kb, *Vt, *Ob;
    cudaGetSymbolAddress((void**)&We, g_We);
    cudaGetSymbolAddress((void**)&X,  g_X);
    cudaGetSymbolAddress((void**)&Qb, g_Q);
    cudaGetSymbolAddress((void**)&Kb, g_K);
    cudaGetSymbolAddress((void**)&Vt, g_Vt);
    cudaGetSymbolAddress((void**)&Ob, g_O);

    cudaFuncSetAttribute(gemm_qkv,
                         cudaFuncAttributeMaxDynamicSharedMemorySize, GEMM_SMEM);
    cudaFuncSetAttribute(gemm_out_sk,
                         cudaFuncAttributeMaxDynamicSharedMemorySize, GEMM_SMEM);
    cudaFuncSetAttribute(flash_mma,
                         cudaFuncAttributeMaxDynamicSharedMemorySize, FLASH_SMEM);

    prep_kernel<<<dim3(DD * DD / 256, 6), 256>>>(wq, wk, wv, wo, x);

    gemm_qkv<<<dim3(DD / 128, MM / 128, 3), 256, GEMM_SMEM>>>(
        X, bq, bk, bv, Qb, Kb, Vt);

    flash_mma<<<dim3(32, 16), 128, FLASH_SMEM>>>(Qb, Kb, Vt, Ob);

    gemm_out_sk<<<dim3(DD / 128, MM / 128, 2), 256, GEMM_SMEM>>>(
        Ob, We + 3 * DD * DD);
    reduce_bias<<<MM * DD / 1024, 256>>>(bo, out);
}